// round 6
// baseline (speedup 1.0000x reference)
#include <cuda_runtime.h>
#include <cstdint>

#define N_PTS    8192
#define N_SMP    2048
#define BATCH    8
#define CHANNELS 128

// FPS cluster decomposition
#define FPS_C    4                    // CTAs per batch (one cluster)
#define FPS_T    256                  // threads per FPS CTA
#define FPS_LOC  (N_PTS / FPS_C)      // 2048 points owned per CTA

// ---- packed f32x2 helpers (two independent rn-rounded f32 ops per instr).
// Fallback path is two scalar rn ops: bit-identical results either way. ----
#if defined(__CUDA_ARCH__) && (__CUDA_ARCH__ >= 1000)
#define HAS_F32X2 1
#else
#define HAS_F32X2 0
#endif

struct P2 { float lo, hi; };

__device__ __forceinline__ P2 pk2(float a, float b) { P2 r; r.lo = a; r.hi = b; return r; }

__device__ __forceinline__ P2 add2(P2 a, P2 b) {
#if HAS_F32X2
    unsigned long long av, bv, rv;
    asm("mov.b64 %0, {%1, %2};" : "=l"(av) : "f"(a.lo), "f"(a.hi));
    asm("mov.b64 %0, {%1, %2};" : "=l"(bv) : "f"(b.lo), "f"(b.hi));
    asm("add.rn.f32x2 %0, %1, %2;" : "=l"(rv) : "l"(av), "l"(bv));
    P2 r;
    asm("mov.b64 {%0, %1}, %2;" : "=f"(r.lo), "=f"(r.hi) : "l"(rv));
    return r;
#else
    P2 r; r.lo = __fadd_rn(a.lo, b.lo); r.hi = __fadd_rn(a.hi, b.hi); return r;
#endif
}

__device__ __forceinline__ P2 mul2(P2 a, P2 b) {
#if HAS_F32X2
    unsigned long long av, bv, rv;
    asm("mov.b64 %0, {%1, %2};" : "=l"(av) : "f"(a.lo), "f"(a.hi));
    asm("mov.b64 %0, {%1, %2};" : "=l"(bv) : "f"(b.lo), "f"(b.hi));
    asm("mul.rn.f32x2 %0, %1, %2;" : "=l"(rv) : "l"(av), "l"(bv));
    P2 r;
    asm("mov.b64 {%0, %1}, %2;" : "=f"(r.lo), "=f"(r.hi) : "l"(rv));
    return r;
#else
    P2 r; r.lo = __fmul_rn(a.lo, b.lo); r.hi = __fmul_rn(a.hi, b.hi); return r;
#endif
}

// ---- cluster / mbarrier helpers -------------------------------------------
__device__ __forceinline__ uint32_t smem_u32(const void* p) {
    uint32_t a;
    asm("{ .reg .u64 t; cvta.to.shared.u64 t, %1; cvt.u32.u64 %0, t; }"
        : "=r"(a) : "l"(p));
    return a;
}
__device__ __forceinline__ uint32_t mapa_u32(uint32_t laddr, uint32_t rank) {
    uint32_t ra;
    asm("mapa.shared::cluster.u32 %0, %1, %2;" : "=r"(ra) : "r"(laddr), "r"(rank));
    return ra;
}
__device__ __forceinline__ void st_cluster_u32(uint32_t addr, uint32_t v) {
    asm volatile("st.shared::cluster.u32 [%0], %1;" :: "r"(addr), "r"(v) : "memory");
}
__device__ __forceinline__ void mbar_init(uint32_t addr, uint32_t cnt) {
    asm volatile("mbarrier.init.shared.b64 [%0], %1;" :: "r"(addr), "r"(cnt) : "memory");
}
__device__ __forceinline__ void mbar_arrive_cluster(uint32_t addr) {
    asm volatile("mbarrier.arrive.release.cluster.shared::cluster.b64 _, [%0];"
                 :: "r"(addr) : "memory");
}
__device__ __forceinline__ void mbar_wait_cluster(uint32_t addr, uint32_t parity) {
    asm volatile(
        "{\n\t"
        ".reg .pred P;\n\t"
        "WL_%=:\n\t"
        "mbarrier.try_wait.parity.acquire.cluster.shared::cta.b64 P, [%0], %1, 0x989680;\n\t"
        "@!P bra WL_%=;\n\t"
        "}"
        :: "r"(addr), "r"(parity) : "memory");
}
__device__ __forceinline__ void cluster_sync_() {
    asm volatile("barrier.cluster.arrive.aligned;" ::: "memory");
    asm volatile("barrier.cluster.wait.aligned;" ::: "memory");
}

// ---------------------------------------------------------------------------
// Kernel 1: farthest point sampling, 4-CTA cluster per batch.
// Each CTA (256 threads) owns 2048 points: 8 register slots/thread packed as
// 4 f32x2 pairs — identical arithmetic to the proven single-CTA version, so
// selection is bit-identical. Per iteration:
//   local packed dist update + argmax -> warp REDUX -> 8 warp candidates
//   -> BAR -> warp0 REDUX -> leader posts (val, gidx, x, y, z) into all 4
//   CTAs' slots (st.shared::cluster) + release-arrives on each CTA's
//   mbarrier -> all threads acquire-wait -> lexicographic combine of 4
//   candidates. Slots + mbarriers are double-buffered (buf = m&1, parity
//   = (m>>1)&1); the arrive dependency chain gates any iter-(m+1) write
//   behind every CTA's iter-m read, so single-phase-skew races cannot occur.
// ---------------------------------------------------------------------------
__global__ void __launch_bounds__(FPS_T, 1) __cluster_dims__(FPS_C, 1, 1)
fps_kernel(const float* __restrict__ pos, float* __restrict__ sampled)
{
    __shared__ float xs[FPS_LOC], ys[FPS_LOC], zs[FPS_LOC];
    __shared__ unsigned s_val[8], s_idx[8];
    __shared__ __align__(8) unsigned long long mbar[2];
    __shared__ __align__(16) unsigned slots[2][FPS_C][8]; // val,idx,x,y,z,pad

    const int b    = blockIdx.x / FPS_C;
    const unsigned rank = blockIdx.x % FPS_C;
    const int t    = threadIdx.x;
    const int lane = t & 31;
    const int warp = t >> 5;
    const int base = rank * FPS_LOC;
    const float* p = pos + (size_t)b * 3 * N_PTS;

    // own points: slot s owns local j = t + s*256; pair q packs (2q, 2q+1)
    P2 x2[4], y2[4], z2[4];
    float dist[8];
    {
        float xv[8], yv[8], zv[8];
#pragma unroll
        for (int s = 0; s < 8; s++) {
            int j = t + (s << 8);
            int g = base + j;
            xv[s] = p[g];
            yv[s] = p[N_PTS + g];
            zv[s] = p[2 * N_PTS + g];
            xs[j] = xv[s];
            ys[j] = yv[s];
            zs[j] = zv[s];
            dist[s] = 1e10f;
        }
#pragma unroll
        for (int q = 0; q < 4; q++) {
            x2[q] = pk2(xv[2 * q], xv[2 * q + 1]);
            y2[q] = pk2(yv[2 * q], yv[2 * q + 1]);
            z2[q] = pk2(zv[2 * q], zv[2 * q + 1]);
        }
    }

    const uint32_t mbarA[2] = { smem_u32(&mbar[0]), smem_u32(&mbar[1]) };
    const uint32_t slotA[2] = { smem_u32(&slots[0][rank][0]),
                                smem_u32(&slots[1][rank][0]) };
    if (t == 0) {
        mbar_init(mbarA[0], FPS_C);
        mbar_init(mbarA[1], FPS_C);
    }
    __syncthreads();
    cluster_sync_();   // all barriers live before any remote arrive

    // initial centroid = global point 0 (idx[0] = 0 in the reference scan)
    float cx = p[0], cy = p[N_PTS], cz = p[2 * N_PTS];

    float* out = sampled + (size_t)b * 3 * N_SMP;

    for (int m = 0; m < N_SMP; m++) {
        if (rank == 0 && t == 0) {
            out[m]             = cx;
            out[N_SMP + m]     = cy;
            out[2 * N_SMP + m] = cz;
        }
        P2 ncx = pk2(-cx, -cx);
        P2 ncy = pk2(-cy, -cy);
        P2 ncz = pk2(-cz, -cz);

        // local update + argmax (dist >= 0: float bits order as u32;
        // strict '>' in ascending local idx keeps first occurrence)
        unsigned bestb = 0u;
        int bidx = t;
#pragma unroll
        for (int q = 0; q < 4; q++) {
            P2 dx = add2(x2[q], ncx);
            P2 dy = add2(y2[q], ncy);
            P2 dz = add2(z2[q], ncz);
            P2 xx = mul2(dx, dx);
            P2 yy = mul2(dy, dy);
            P2 zz = mul2(dz, dz);
            P2 d2 = add2(add2(xx, yy), zz);
            float nlo = fminf(dist[2 * q], d2.lo);
            float nhi = fminf(dist[2 * q + 1], d2.hi);
            dist[2 * q]     = nlo;
            dist[2 * q + 1] = nhi;
            unsigned blo = __float_as_uint(nlo);
            if (blo > bestb) { bestb = blo; bidx = t + (q << 9); }
            unsigned bhi = __float_as_uint(nhi);
            if (bhi > bestb) { bestb = bhi; bidx = t + (q << 9) + 256; }
        }

        unsigned wmax = __reduce_max_sync(0xffffffffu, bestb);
        unsigned cand = (bestb == wmax) ? (unsigned)bidx : 0xffffffffu;
        unsigned widx = __reduce_min_sync(0xffffffffu, cand);
        if (lane == 0) { s_val[warp] = wmax; s_idx[warp] = widx; }
        __syncthreads();

        const int buf = m & 1;

        if (warp == 0) {
            unsigned v = (lane < 8) ? s_val[lane] : 0u;
            unsigned i = (lane < 8) ? s_idx[lane] : 0xffffffffu;
            unsigned cmax = __reduce_max_sync(0xffffffffu, v);
            unsigned cc   = (v == cmax) ? i : 0xffffffffu;
            unsigned clid = __reduce_min_sync(0xffffffffu, cc);
            if (lane == 0) {
                float wx = xs[clid], wy = ys[clid], wz = zs[clid];
                unsigned gidx = (unsigned)base + clid;
#pragma unroll
                for (unsigned r = 0; r < FPS_C; r++) {
                    uint32_t sa = mapa_u32(slotA[buf], r);
                    st_cluster_u32(sa +  0, cmax);
                    st_cluster_u32(sa +  4, gidx);
                    st_cluster_u32(sa +  8, __float_as_uint(wx));
                    st_cluster_u32(sa + 12, __float_as_uint(wy));
                    st_cluster_u32(sa + 16, __float_as_uint(wz));
                }
#pragma unroll
                for (unsigned r = 0; r < FPS_C; r++)
                    mbar_arrive_cluster(mapa_u32(mbarA[buf], r));
            }
        }

        // all threads wait for the 4 leader arrivals, then combine locally
        mbar_wait_cluster(mbarA[buf], (unsigned)((m >> 1) & 1));

        unsigned bv = slots[buf][0][0];
        unsigned bg = slots[buf][0][1];
        int br = 0;
#pragma unroll
        for (int r = 1; r < FPS_C; r++) {
            unsigned v = slots[buf][r][0];
            unsigned g = slots[buf][r][1];
            if (v > bv || (v == bv && g < bg)) { bv = v; bg = g; br = r; }
        }
        cx = __uint_as_float(slots[buf][br][2]);
        cy = __uint_as_float(slots[buf][br][3]);
        cz = __uint_as_float(slots[buf][br][4]);
    }
    cluster_sync_();   // no CTA exits while peers' remote ops may be in flight
}

// ---------------------------------------------------------------------------
// Kernel 2: 4-NN + channel max-pool, full-chip version (unchanged).
// ---------------------------------------------------------------------------
#define CHUNK_PTS 4096

__global__ void __launch_bounds__(256, 2)
knn_pool_kernel(const float* __restrict__ feats,
                const float* __restrict__ pos,
                const float* __restrict__ sampled,
                float* __restrict__ pooled)
{
    extern __shared__ float4 tile[];   // [4096] = 64 KB: (x, y, z, p2)

    const int b = blockIdx.y;
    const int t = threadIdx.x;
    const int part = t & 3;
    const int q = blockIdx.x * 64 + (t >> 2);

    const float* sp = sampled + (size_t)b * 3 * N_SMP;
    float sx = sp[q];
    float sy = sp[N_SMP + q];
    float sz = sp[2 * N_SMP + q];
    float s2 = __fadd_rn(__fadd_rn(__fmul_rn(sx, sx), __fmul_rn(sy, sy)),
                         __fmul_rn(sz, sz));

    const float* p = pos + (size_t)b * 3 * N_PTS;

    const float INF = __int_as_float(0x7f800000);
    float d0 = INF, d1 = INF, d2 = INF, d3 = INF;
    int   i0 = 0x7fffffff, i1 = 0x7fffffff, i2 = 0x7fffffff, i3 = 0x7fffffff;

    for (int chunk = 0; chunk < N_PTS / CHUNK_PTS; chunk++) {
        const int base = chunk * CHUNK_PTS;
        __syncthreads();
        for (int j = t; j < CHUNK_PTS; j += 256) {
            int g = base + j;
            float px = p[g];
            float py = p[N_PTS + g];
            float pz = p[2 * N_PTS + g];
            float p2 = __fadd_rn(__fadd_rn(__fmul_rn(px, px), __fmul_rn(py, py)),
                                 __fmul_rn(pz, pz));
            tile[j] = make_float4(px, py, pz, p2);
        }
        __syncthreads();

#pragma unroll 4
        for (int i = 0; i < CHUNK_PTS / 4; i++) {
            int e = (i << 2) + part;
            float4 pt = tile[e];
            float cross = __fadd_rn(__fadd_rn(__fmul_rn(sx, pt.x), __fmul_rn(sy, pt.y)),
                                    __fmul_rn(sz, pt.z));
            float dv = __fsub_rn(__fadd_rn(s2, pt.w), __fmul_rn(2.0f, cross));
            if (dv < d3) {
                int j = base + e;
                if (dv < d2) {
                    d3 = d2; i3 = i2;
                    if (dv < d1) {
                        d2 = d1; i2 = i1;
                        if (dv < d0) { d1 = d0; i1 = i0; d0 = dv; i0 = j; }
                        else         { d1 = dv; i1 = j; }
                    } else { d2 = dv; i2 = j; }
                } else { d3 = dv; i3 = j; }
            }
        }
    }

    int mi[4];
#pragma unroll
    for (int r = 0; r < 4; r++) {
        float hd = d0;
        int   hi = i0;
#pragma unroll
        for (int off = 1; off < 4; off <<= 1) {
            float od = __shfl_xor_sync(0xffffffffu, hd, off, 4);
            int   oi = __shfl_xor_sync(0xffffffffu, hi, off, 4);
            if (od < hd || (od == hd && oi < hi)) { hd = od; hi = oi; }
        }
        mi[r] = hi;
        if (hi == i0) {
            d0 = d1; i0 = i1;
            d1 = d2; i1 = i2;
            d2 = d3; i2 = i3;
            d3 = INF; i3 = 0x7fffffff;
        }
    }

    const float* f0 = feats + (size_t)b * CHANNELS * N_PTS;
    float* outp = pooled + (size_t)b * CHANNELS * N_SMP + q;
#pragma unroll 4
    for (int cc = 0; cc < CHANNELS / 4; cc++) {
        int c = part * (CHANNELS / 4) + cc;
        const float* fc = f0 + (size_t)c * N_PTS;
        float v = fmaxf(fmaxf(__ldg(fc + mi[0]), __ldg(fc + mi[1])),
                        fmaxf(__ldg(fc + mi[2]), __ldg(fc + mi[3])));
        outp[(size_t)c * N_SMP] = v;
    }
}

// ---------------------------------------------------------------------------
// Launch
// ---------------------------------------------------------------------------
extern "C" void kernel_launch(void* const* d_in, const int* in_sizes, int n_in,
                              void* d_out, int out_size)
{
    const float* feats = (const float*)d_in[0];   // (8,128,8192)
    const float* pos   = (const float*)d_in[1];   // (8,3,8192)

    float* pooled  = (float*)d_out;                                    // (8,128,2048)
    float* sampled = (float*)d_out + (size_t)BATCH * CHANNELS * N_SMP; // (8,3,2048)

    const int knn_smem = CHUNK_PTS * (int)sizeof(float4);       // 64 KB
    cudaFuncSetAttribute(knn_pool_kernel,
                         cudaFuncAttributeMaxDynamicSharedMemorySize, knn_smem);

    fps_kernel<<<BATCH * FPS_C, FPS_T>>>(pos, sampled);

    dim3 grid(N_SMP / 64, BATCH);
    knn_pool_kernel<<<grid, 256, knn_smem>>>(feats, pos, sampled, pooled);
}

// round 7
// speedup vs baseline: 2.5327x; 2.5327x over previous
#include <cuda_runtime.h>
#include <cstdint>

#define N_PTS    8192
#define N_SMP    2048
#define BATCH    8
#define CHANNELS 128

// KNN decomposition inside the fused kernel
#define KNN_CTAS_PER_BATCH 32          // 256 queries per CTA
#define KNN_Q_PER_CTA      256
#define CHUNK_PTS          4096

// device-global scratch (sanctioned workaround for no-malloc rule)
__device__ int   g_idx[BATCH * N_SMP];                        // FPS sample indices
__device__ float g_allpooled[(size_t)BATCH * CHANNELS * N_PTS]; // pooled feats for ALL points

// ---- packed f32x2 helpers (two independent rn-rounded f32 ops per instr).
// Fallback path is two scalar rn ops: bit-identical results either way. ----
#if defined(__CUDA_ARCH__) && (__CUDA_ARCH__ >= 1000)
#define HAS_F32X2 1
#else
#define HAS_F32X2 0
#endif

struct P2 { float lo, hi; };

__device__ __forceinline__ P2 pk2(float a, float b) { P2 r; r.lo = a; r.hi = b; return r; }

__device__ __forceinline__ P2 add2(P2 a, P2 b) {
#if HAS_F32X2
    unsigned long long av, bv, rv;
    asm("mov.b64 %0, {%1, %2};" : "=l"(av) : "f"(a.lo), "f"(a.hi));
    asm("mov.b64 %0, {%1, %2};" : "=l"(bv) : "f"(b.lo), "f"(b.hi));
    asm("add.rn.f32x2 %0, %1, %2;" : "=l"(rv) : "l"(av), "l"(bv));
    P2 r;
    asm("mov.b64 {%0, %1}, %2;" : "=f"(r.lo), "=f"(r.hi) : "l"(rv));
    return r;
#else
    P2 r; r.lo = __fadd_rn(a.lo, b.lo); r.hi = __fadd_rn(a.hi, b.hi); return r;
#endif
}

__device__ __forceinline__ P2 mul2(P2 a, P2 b) {
#if HAS_F32X2
    unsigned long long av, bv, rv;
    asm("mov.b64 %0, {%1, %2};" : "=l"(av) : "f"(a.lo), "f"(a.hi));
    asm("mov.b64 %0, {%1, %2};" : "=l"(bv) : "f"(b.lo), "f"(b.hi));
    asm("mul.rn.f32x2 %0, %1, %2;" : "=l"(rv) : "l"(av), "l"(bv));
    P2 r;
    asm("mov.b64 {%0, %1}, %2;" : "=f"(r.lo), "=f"(r.hi) : "l"(rv));
    return r;
#else
    P2 r; r.lo = __fmul_rn(a.lo, b.lo); r.hi = __fmul_rn(a.hi, b.hi); return r;
#endif
}

// ---------------------------------------------------------------------------
// FPS body: exact Round-5 single-CTA version (bit-exact, rel_err 0.0),
// plus one extra int store of the entering `far` index for the epilogue.
// ---------------------------------------------------------------------------
__device__ void fps_body(const float* __restrict__ pos,
                         float* __restrict__ sampled,
                         float* smem, int b)
{
    float* xs = smem;                 // [8192]
    float* ys = smem + N_PTS;         // [8192]
    float* zs = smem + 2 * N_PTS;     // [8192]
    __shared__ unsigned s_val[2][32];
    __shared__ unsigned s_idx[2][32];

    const int t = threadIdx.x;
    const int lane = t & 31;
    const int warp = t >> 5;
    const float* p = pos + (size_t)b * 3 * N_PTS;

    P2 x2[4], y2[4], z2[4];
    float dist[8];
    {
        float xv[8], yv[8], zv[8];
#pragma unroll
        for (int s = 0; s < 8; s++) {
            int j = t + (s << 10);
            xv[s] = p[j];
            yv[s] = p[N_PTS + j];
            zv[s] = p[2 * N_PTS + j];
            xs[j] = xv[s];
            ys[j] = yv[s];
            zs[j] = zv[s];
            dist[s] = 1e10f;
        }
#pragma unroll
        for (int q = 0; q < 4; q++) {
            x2[q] = pk2(xv[2 * q], xv[2 * q + 1]);
            y2[q] = pk2(yv[2 * q], yv[2 * q + 1]);
            z2[q] = pk2(zv[2 * q], zv[2 * q + 1]);
        }
    }
    __syncthreads();

    int far = 0;
    int buf = 0;
    float* out = sampled + (size_t)b * 3 * N_SMP;
    int* idxout = g_idx + b * N_SMP;

    for (int m = 0; m < N_SMP; m++) {
        float cx = xs[far], cy = ys[far], cz = zs[far];
        if (t == 0) {
            out[m]             = cx;
            out[N_SMP + m]     = cy;
            out[2 * N_SMP + m] = cz;
            idxout[m]          = far;
        }
        P2 ncx = pk2(-cx, -cx);
        P2 ncy = pk2(-cy, -cy);
        P2 ncz = pk2(-cz, -cz);

        unsigned bestb = 0u;
        int bidx = t;
#pragma unroll
        for (int q = 0; q < 4; q++) {
            P2 dx = add2(x2[q], ncx);
            P2 dy = add2(y2[q], ncy);
            P2 dz = add2(z2[q], ncz);
            P2 xx = mul2(dx, dx);
            P2 yy = mul2(dy, dy);
            P2 zz = mul2(dz, dz);
            P2 d2 = add2(add2(xx, yy), zz);
            float nlo = fminf(dist[2 * q], d2.lo);
            float nhi = fminf(dist[2 * q + 1], d2.hi);
            dist[2 * q]     = nlo;
            dist[2 * q + 1] = nhi;
            unsigned blo = __float_as_uint(nlo);
            if (blo > bestb) { bestb = blo; bidx = t + (q << 11); }
            unsigned bhi = __float_as_uint(nhi);
            if (bhi > bestb) { bestb = bhi; bidx = t + (q << 11) + 1024; }
        }

        unsigned wmax = __reduce_max_sync(0xffffffffu, bestb);
        unsigned cand = (bestb == wmax) ? (unsigned)bidx : 0xffffffffu;
        unsigned widx = __reduce_min_sync(0xffffffffu, cand);
        if (lane == 0) { s_val[buf][warp] = wmax; s_idx[buf][warp] = widx; }
        __syncthreads();

        unsigned v = s_val[buf][lane];
        unsigned i = s_idx[buf][lane];
        unsigned gmax = __reduce_max_sync(0xffffffffu, v);
        unsigned gc   = (v == gmax) ? i : 0xffffffffu;
        far = (int)__reduce_min_sync(0xffffffffu, gc);
        buf ^= 1;
    }
}

// ---------------------------------------------------------------------------
// All-pairs KNN body: 4-NN + channel max-pool for EVERY input point.
// 1024 threads, 256 queries/CTA, 4 parts/query (part p scans cand e = 4i+p:
// consecutive float4s per 4-lane group -> conflict-free broadcast LDS).
// Same arithmetic / tie-break as the proven 2048-query kernel, so rows are
// identical to the reference's dist rows; results land in g_allpooled.
// ---------------------------------------------------------------------------
__device__ void allknn_body(const float* __restrict__ feats,
                            const float* __restrict__ pos,
                            float* smem, int cta)
{
    float4* tile = (float4*)smem;      // [4096] = 64 KB of the 96 KB alloc

    const int b    = cta / KNN_CTAS_PER_BATCH;
    const int qblk = cta % KNN_CTAS_PER_BATCH;
    const int t    = threadIdx.x;
    const int part = t & 3;
    const int q    = qblk * KNN_Q_PER_CTA + (t >> 2);   // 0..8191

    const float* p = pos + (size_t)b * 3 * N_PTS;
    float sx = p[q];
    float sy = p[N_PTS + q];
    float sz = p[2 * N_PTS + q];
    float s2 = __fadd_rn(__fadd_rn(__fmul_rn(sx, sx), __fmul_rn(sy, sy)),
                         __fmul_rn(sz, sz));

    const float INF = __int_as_float(0x7f800000);
    float d0 = INF, d1 = INF, d2 = INF, d3 = INF;
    int   i0 = 0x7fffffff, i1 = 0x7fffffff, i2 = 0x7fffffff, i3 = 0x7fffffff;

    for (int chunk = 0; chunk < N_PTS / CHUNK_PTS; chunk++) {
        const int base = chunk * CHUNK_PTS;
        __syncthreads();   // previous chunk fully consumed before overwrite
        for (int j = t; j < CHUNK_PTS; j += 1024) {
            int g = base + j;
            float px = p[g];
            float py = p[N_PTS + g];
            float pz = p[2 * N_PTS + g];
            float p2 = __fadd_rn(__fadd_rn(__fmul_rn(px, px), __fmul_rn(py, py)),
                                 __fmul_rn(pz, pz));
            tile[j] = make_float4(px, py, pz, p2);
        }
        __syncthreads();

        // ascending global idx within a part -> '<' keeps first occurrence
#pragma unroll 4
        for (int i = 0; i < CHUNK_PTS / 4; i++) {
            int e = (i << 2) + part;
            float4 pt = tile[e];
            float cross = __fadd_rn(__fadd_rn(__fmul_rn(sx, pt.x), __fmul_rn(sy, pt.y)),
                                    __fmul_rn(sz, pt.z));
            float dv = __fsub_rn(__fadd_rn(s2, pt.w), __fmul_rn(2.0f, cross));
            if (dv < d3) {
                int j = base + e;
                if (dv < d2) {
                    d3 = d2; i3 = i2;
                    if (dv < d1) {
                        d2 = d1; i2 = i1;
                        if (dv < d0) { d1 = d0; i1 = i0; d0 = dv; i0 = j; }
                        else         { d1 = dv; i1 = j; }
                    } else { d2 = dv; i2 = j; }
                } else { d3 = dv; i3 = j; }
            }
        }
    }

    // merge 4 per-part sorted lists: 4 rounds of (d, idx)-lexicographic min
    int mi[4];
#pragma unroll
    for (int r = 0; r < 4; r++) {
        float hd = d0;
        int   hi = i0;
#pragma unroll
        for (int off = 1; off < 4; off <<= 1) {
            float od = __shfl_xor_sync(0xffffffffu, hd, off, 4);
            int   oi = __shfl_xor_sync(0xffffffffu, hi, off, 4);
            if (od < hd || (od == hd && oi < hi)) { hd = od; hi = oi; }
        }
        mi[r] = hi;
        if (hi == i0) {   // global indices unique -> exact pop test
            d0 = d1; i0 = i1;
            d1 = d2; i1 = i2;
            d2 = d3; i2 = i3;
            d3 = INF; i3 = 0x7fffffff;
        }
    }

    // each part max-pools its own 32 channels into the all-points buffer
    const float* f0 = feats + (size_t)b * CHANNELS * N_PTS;
    float* gp = g_allpooled + (size_t)b * CHANNELS * N_PTS + q;
#pragma unroll 4
    for (int cc = 0; cc < CHANNELS / 4; cc++) {
        int c = part * (CHANNELS / 4) + cc;
        const float* fc = f0 + (size_t)c * N_PTS;
        float v = fmaxf(fmaxf(__ldg(fc + mi[0]), __ldg(fc + mi[1])),
                        fmaxf(__ldg(fc + mi[2]), __ldg(fc + mi[3])));
        gp[(size_t)c * N_PTS] = v;
    }
}

// ---------------------------------------------------------------------------
// Fused kernel: bids 0..7 = FPS (one per batch, wave-1 scheduled);
// bids 8..263 = all-pairs KNN (runs concurrently on the idle SMs and
// finishes well before FPS; no dependency between the two paths).
// ---------------------------------------------------------------------------
__global__ void __launch_bounds__(1024, 1)
fused_kernel(const float* __restrict__ feats,
             const float* __restrict__ pos,
             float* __restrict__ sampled)
{
    extern __shared__ float smem[];
    if (blockIdx.x < BATCH) {
        fps_body(pos, sampled, smem, blockIdx.x);
    } else {
        allknn_body(feats, pos, smem, blockIdx.x - BATCH);
    }
}

// ---------------------------------------------------------------------------
// Epilogue: pooled[b,c,m] = allpooled[b,c, idx[b,m]]. allpooled is hot in
// L2 (just written), so this is a ~2M-element L2 gather.
// ---------------------------------------------------------------------------
__global__ void __launch_bounds__(256)
gather_kernel(float* __restrict__ pooled)
{
    int gid = blockIdx.x * 256 + threadIdx.x;       // over 8*128*2048
    int m  = gid & (N_SMP - 1);
    int bc = gid >> 11;                             // b*128 + c
    int b  = bc >> 7;
    int i  = g_idx[b * N_SMP + m];
    pooled[gid] = g_allpooled[(size_t)bc * N_PTS + i];
}

// ---------------------------------------------------------------------------
// Launch
// ---------------------------------------------------------------------------
extern "C" void kernel_launch(void* const* d_in, const int* in_sizes, int n_in,
                              void* d_out, int out_size)
{
    const float* feats = (const float*)d_in[0];   // (8,128,8192)
    const float* pos   = (const float*)d_in[1];   // (8,3,8192)

    float* pooled  = (float*)d_out;                                    // (8,128,2048)
    float* sampled = (float*)d_out + (size_t)BATCH * CHANNELS * N_SMP; // (8,3,2048)

    const int fused_smem = 3 * N_PTS * (int)sizeof(float);   // 96 KB
    cudaFuncSetAttribute(fused_kernel,
                         cudaFuncAttributeMaxDynamicSharedMemorySize, fused_smem);

    const int n_ctas = BATCH + BATCH * KNN_CTAS_PER_BATCH;   // 8 + 256
    fused_kernel<<<n_ctas, 1024, fused_smem>>>(feats, pos, sampled);

    gather_kernel<<<(BATCH * CHANNELS * N_SMP) / 256, 256>>>(pooled);
}

// round 8
// speedup vs baseline: 2.6347x; 1.0403x over previous
#include <cuda_runtime.h>
#include <cstdint>

#define N_PTS    8192
#define N_SMP    2048
#define BATCH    8
#define CHANNELS 128

// KNN decomposition inside the fused kernel
#define KNN_CTAS_PER_BATCH 32          // 256 queries per CTA
#define KNN_Q_PER_CTA      256
#define CHUNK_PTS          4096

// force 1 CTA/SM (2 x 116KB > 227KB): FPS CTAs never share an SM with KNN
#define FUSED_SMEM_BYTES   (116 * 1024)

// device-global scratch (sanctioned workaround for no-malloc rule)
__device__ int   g_idx[BATCH * N_SMP];                          // FPS sample indices
__device__ float g_allpooled[(size_t)BATCH * CHANNELS * N_PTS]; // pooled feats, ALL points

// ---- packed f32x2 helpers (two independent rn-rounded f32 ops per instr).
// Fallback is two scalar rn ops: bit-identical either way. ----
#if defined(__CUDA_ARCH__) && (__CUDA_ARCH__ >= 1000)
#define HAS_F32X2 1
#else
#define HAS_F32X2 0
#endif

struct P2 { float lo, hi; };

__device__ __forceinline__ P2 pk2(float a, float b) { P2 r; r.lo = a; r.hi = b; return r; }

__device__ __forceinline__ P2 add2(P2 a, P2 b) {
#if HAS_F32X2
    unsigned long long av, bv, rv;
    asm("mov.b64 %0, {%1, %2};" : "=l"(av) : "f"(a.lo), "f"(a.hi));
    asm("mov.b64 %0, {%1, %2};" : "=l"(bv) : "f"(b.lo), "f"(b.hi));
    asm("add.rn.f32x2 %0, %1, %2;" : "=l"(rv) : "l"(av), "l"(bv));
    P2 r;
    asm("mov.b64 {%0, %1}, %2;" : "=f"(r.lo), "=f"(r.hi) : "l"(rv));
    return r;
#else
    P2 r; r.lo = __fadd_rn(a.lo, b.lo); r.hi = __fadd_rn(a.hi, b.hi); return r;
#endif
}

__device__ __forceinline__ P2 sub2(P2 a, P2 b) {
#if HAS_F32X2
    unsigned long long av, bv, rv;
    asm("mov.b64 %0, {%1, %2};" : "=l"(av) : "f"(a.lo), "f"(a.hi));
    asm("mov.b64 %0, {%1, %2};" : "=l"(bv) : "f"(b.lo), "f"(b.hi));
    asm("sub.rn.f32x2 %0, %1, %2;" : "=l"(rv) : "l"(av), "l"(bv));
    P2 r;
    asm("mov.b64 {%0, %1}, %2;" : "=f"(r.lo), "=f"(r.hi) : "l"(rv));
    return r;
#else
    P2 r; r.lo = __fsub_rn(a.lo, b.lo); r.hi = __fsub_rn(a.hi, b.hi); return r;
#endif
}

__device__ __forceinline__ P2 mul2(P2 a, P2 b) {
#if HAS_F32X2
    unsigned long long av, bv, rv;
    asm("mov.b64 %0, {%1, %2};" : "=l"(av) : "f"(a.lo), "f"(a.hi));
    asm("mov.b64 %0, {%1, %2};" : "=l"(bv) : "f"(b.lo), "f"(b.hi));
    asm("mul.rn.f32x2 %0, %1, %2;" : "=l"(rv) : "l"(av), "l"(bv));
    P2 r;
    asm("mov.b64 {%0, %1}, %2;" : "=f"(r.lo), "=f"(r.hi) : "l"(rv));
    return r;
#else
    P2 r; r.lo = __fmul_rn(a.lo, b.lo); r.hi = __fmul_rn(a.hi, b.hi); return r;
#endif
}

// ---------------------------------------------------------------------------
// FPS body: single CTA (1024 threads) per batch, bit-exact selection.
// vs Round 5/7: sub.rn.f32x2 (drops 3 NEGs; IEEE x-c == x+(-c) so bits
// unchanged), (val,idx) packed as one u64 STS/LDS, cloud as float2 xy +
// float z (2 LDS at iter start), and NO coordinate STGs in the loop (only
// g_idx; gather epilogue reconstructs sampled_pos verbatim from pos).
// ---------------------------------------------------------------------------
__device__ void fps_body(const float* __restrict__ pos, char* smem, int b)
{
    float2* xy = (float2*)smem;                    // [8192]  64 KB
    float*  zs = (float*)(smem + N_PTS * 8);       // [8192]  32 KB
    __shared__ unsigned long long s_cand[2][32];   // (valbits<<32)|idx

    const int t = threadIdx.x;
    const int lane = t & 31;
    const int warp = t >> 5;
    const float* p = pos + (size_t)b * 3 * N_PTS;

    // slot s owns point j = t + s*1024; pair q packs slots (2q, 2q+1)
    P2 x2[4], y2[4], z2[4];
    float dist[8];
    {
        float xv[8], yv[8], zv[8];
#pragma unroll
        for (int s = 0; s < 8; s++) {
            int j = t + (s << 10);
            xv[s] = p[j];
            yv[s] = p[N_PTS + j];
            zv[s] = p[2 * N_PTS + j];
            xy[j] = make_float2(xv[s], yv[s]);
            zs[j] = zv[s];
            dist[s] = 1e10f;   // reference init 10000000000.0
        }
#pragma unroll
        for (int q = 0; q < 4; q++) {
            x2[q] = pk2(xv[2 * q], xv[2 * q + 1]);
            y2[q] = pk2(yv[2 * q], yv[2 * q + 1]);
            z2[q] = pk2(zv[2 * q], zv[2 * q + 1]);
        }
    }
    __syncthreads();

    int far = 0;
    int buf = 0;
    int* idxout = g_idx + b * N_SMP;

    for (int m = 0; m < N_SMP; m++) {
        float2 cxy = xy[far];
        float  cz  = zs[far];
        if (t == 0) idxout[m] = far;   // scan emits `farthest` at step entry
        P2 cxx = pk2(cxy.x, cxy.x);
        P2 cyy = pk2(cxy.y, cxy.y);
        P2 czz = pk2(cz, cz);

        // dist >= 0: float bits order as u32; strict '>' in ascending
        // slot order keeps first occurrence (jnp.argmax semantics).
        unsigned bestb = 0u;
        int bidx = t;
#pragma unroll
        for (int q = 0; q < 4; q++) {
            P2 dx = sub2(x2[q], cxx);
            P2 dy = sub2(y2[q], cyy);
            P2 dz = sub2(z2[q], czz);
            P2 xx = mul2(dx, dx);
            P2 yy = mul2(dy, dy);
            P2 zz = mul2(dz, dz);
            P2 d2 = add2(add2(xx, yy), zz);   // ((xx+yy)+zz), each rn
            float nlo = fminf(dist[2 * q], d2.lo);
            float nhi = fminf(dist[2 * q + 1], d2.hi);
            dist[2 * q]     = nlo;
            dist[2 * q + 1] = nhi;
            unsigned blo = __float_as_uint(nlo);
            if (blo > bestb) { bestb = blo; bidx = t + (q << 11); }
            unsigned bhi = __float_as_uint(nhi);
            if (bhi > bestb) { bestb = bhi; bidx = t + (q << 11) + 1024; }
        }

        // warp argmax via REDUX: max value bits, min idx among matches
        unsigned wmax = __reduce_max_sync(0xffffffffu, bestb);
        unsigned cand = (bestb == wmax) ? (unsigned)bidx : 0xffffffffu;
        unsigned widx = __reduce_min_sync(0xffffffffu, cand);
        if (lane == 0)
            s_cand[buf][warp] = ((unsigned long long)wmax << 32) | widx;
        __syncthreads();

        // every warp redundantly combines the 32 candidates (double-buffered)
        unsigned long long c64 = s_cand[buf][lane];
        unsigned v = (unsigned)(c64 >> 32);
        unsigned i = (unsigned)c64;
        unsigned gmax = __reduce_max_sync(0xffffffffu, v);
        unsigned gc   = (v == gmax) ? i : 0xffffffffu;
        far = (int)__reduce_min_sync(0xffffffffu, gc);
        buf ^= 1;
    }
}

// ---------------------------------------------------------------------------
// All-pairs KNN body: 4-NN + channel max-pool for EVERY input point
// (sampled queries are input points, so query m's row == point idx[m]'s row
// under the reference's own dist formula). Unchanged from Round 7.
// ---------------------------------------------------------------------------
__device__ void allknn_body(const float* __restrict__ feats,
                            const float* __restrict__ pos,
                            char* smem, int cta)
{
    float4* tile = (float4*)smem;      // [4096] = 64 KB of the alloc

    const int b    = cta / KNN_CTAS_PER_BATCH;
    const int qblk = cta % KNN_CTAS_PER_BATCH;
    const int t    = threadIdx.x;
    const int part = t & 3;
    const int q    = qblk * KNN_Q_PER_CTA + (t >> 2);   // 0..8191

    const float* p = pos + (size_t)b * 3 * N_PTS;
    float sx = p[q];
    float sy = p[N_PTS + q];
    float sz = p[2 * N_PTS + q];
    float s2 = __fadd_rn(__fadd_rn(__fmul_rn(sx, sx), __fmul_rn(sy, sy)),
                         __fmul_rn(sz, sz));

    const float INF = __int_as_float(0x7f800000);
    float d0 = INF, d1 = INF, d2 = INF, d3 = INF;
    int   i0 = 0x7fffffff, i1 = 0x7fffffff, i2 = 0x7fffffff, i3 = 0x7fffffff;

    for (int chunk = 0; chunk < N_PTS / CHUNK_PTS; chunk++) {
        const int base = chunk * CHUNK_PTS;
        __syncthreads();   // previous chunk fully consumed before overwrite
        for (int j = t; j < CHUNK_PTS; j += 1024) {
            int g = base + j;
            float px = p[g];
            float py = p[N_PTS + g];
            float pz = p[2 * N_PTS + g];
            float p2 = __fadd_rn(__fadd_rn(__fmul_rn(px, px), __fmul_rn(py, py)),
                                 __fmul_rn(pz, pz));
            tile[j] = make_float4(px, py, pz, p2);
        }
        __syncthreads();

        // ascending global idx within a part -> '<' keeps first occurrence
#pragma unroll 4
        for (int i = 0; i < CHUNK_PTS / 4; i++) {
            int e = (i << 2) + part;
            float4 pt = tile[e];
            float cross = __fadd_rn(__fadd_rn(__fmul_rn(sx, pt.x), __fmul_rn(sy, pt.y)),
                                    __fmul_rn(sz, pt.z));
            float dv = __fsub_rn(__fadd_rn(s2, pt.w), __fmul_rn(2.0f, cross));
            if (dv < d3) {
                int j = base + e;
                if (dv < d2) {
                    d3 = d2; i3 = i2;
                    if (dv < d1) {
                        d2 = d1; i2 = i1;
                        if (dv < d0) { d1 = d0; i1 = i0; d0 = dv; i0 = j; }
                        else         { d1 = dv; i1 = j; }
                    } else { d2 = dv; i2 = j; }
                } else { d3 = dv; i3 = j; }
            }
        }
    }

    // merge 4 per-part sorted lists: 4 rounds of (d, idx)-lexicographic min
    int mi[4];
#pragma unroll
    for (int r = 0; r < 4; r++) {
        float hd = d0;
        int   hi = i0;
#pragma unroll
        for (int off = 1; off < 4; off <<= 1) {
            float od = __shfl_xor_sync(0xffffffffu, hd, off, 4);
            int   oi = __shfl_xor_sync(0xffffffffu, hi, off, 4);
            if (od < hd || (od == hd && oi < hi)) { hd = od; hi = oi; }
        }
        mi[r] = hi;
        if (hi == i0) {   // global indices unique -> exact pop test
            d0 = d1; i0 = i1;
            d1 = d2; i1 = i2;
            d2 = d3; i2 = i3;
            d3 = INF; i3 = 0x7fffffff;
        }
    }

    // each part max-pools its own 32 channels into the all-points buffer
    const float* f0 = feats + (size_t)b * CHANNELS * N_PTS;
    float* gp = g_allpooled + (size_t)b * CHANNELS * N_PTS + q;
#pragma unroll 4
    for (int cc = 0; cc < CHANNELS / 4; cc++) {
        int c = part * (CHANNELS / 4) + cc;
        const float* fc = f0 + (size_t)c * N_PTS;
        float v = fmaxf(fmaxf(__ldg(fc + mi[0]), __ldg(fc + mi[1])),
                        fmaxf(__ldg(fc + mi[2]), __ldg(fc + mi[3])));
        gp[(size_t)c * N_PTS] = v;
    }
}

// ---------------------------------------------------------------------------
// Fused kernel: bids 0..7 = FPS (one per batch); bids 8..263 = all-pairs
// KNN (concurrent on the other SMs, finishes well inside the FPS window).
// 116 KB dynamic smem forces 1 CTA/SM -> FPS never shares an SM with KNN.
// ---------------------------------------------------------------------------
__global__ void __launch_bounds__(1024, 1)
fused_kernel(const float* __restrict__ feats,
             const float* __restrict__ pos)
{
    extern __shared__ char smem[];
    if (blockIdx.x < BATCH) {
        fps_body(pos, smem, blockIdx.x);
    } else {
        allknn_body(feats, pos, smem, blockIdx.x - BATCH);
    }
}

// ---------------------------------------------------------------------------
// Epilogue: pooled[b,c,m] = allpooled[b,c, idx[b,m]]  (L2-hot gather) and
// sampled[b,r,m] = pos[b,r, idx[b,m]]  (verbatim coord copy, bit-identical
// to what the FPS loop used to store).
// ---------------------------------------------------------------------------
#define POOL_ELEMS (BATCH * CHANNELS * N_SMP)      // 2,097,152
#define SMP_ELEMS  (BATCH * 3 * N_SMP)             // 49,152

__global__ void __launch_bounds__(256)
gather_kernel(const float* __restrict__ pos,
              float* __restrict__ pooled,
              float* __restrict__ sampled)
{
    int gid = blockIdx.x * 256 + threadIdx.x;
    if (gid < POOL_ELEMS) {
        int m  = gid & (N_SMP - 1);
        int bc = gid >> 11;                        // b*128 + c
        int b  = bc >> 7;
        int i  = g_idx[b * N_SMP + m];
        pooled[gid] = g_allpooled[(size_t)bc * N_PTS + i];
    } else {
        int sid = gid - POOL_ELEMS;
        int m = sid & (N_SMP - 1);
        int br = sid >> 11;                        // b*3 + r
        int b  = br / 3;
        int r  = br - 3 * b;
        int i  = g_idx[b * N_SMP + m];
        sampled[sid] = pos[((size_t)b * 3 + r) * N_PTS + i];
    }
}

// ---------------------------------------------------------------------------
// Launch
// ---------------------------------------------------------------------------
extern "C" void kernel_launch(void* const* d_in, const int* in_sizes, int n_in,
                              void* d_out, int out_size)
{
    const float* feats = (const float*)d_in[0];   // (8,128,8192)
    const float* pos   = (const float*)d_in[1];   // (8,3,8192)

    float* pooled  = (float*)d_out;                                    // (8,128,2048)
    float* sampled = (float*)d_out + (size_t)BATCH * CHANNELS * N_SMP; // (8,3,2048)

    cudaFuncSetAttribute(fused_kernel,
                         cudaFuncAttributeMaxDynamicSharedMemorySize,
                         FUSED_SMEM_BYTES);

    const int n_ctas = BATCH + BATCH * KNN_CTAS_PER_BATCH;   // 264
    fused_kernel<<<n_ctas, 1024, FUSED_SMEM_BYTES>>>(feats, pos);

    const int tot = POOL_ELEMS + SMP_ELEMS;                  // 2,146,304
    gather_kernel<<<tot / 256, 256>>>(pos, pooled, sampled);
}